// round 1
// baseline (speedup 1.0000x reference)
#include <cuda_runtime.h>
#include <math.h>

#define BB 64
#define NN 40
#define WW 256
#define FIN 64
#define HH 4
#define CC 128
#define WKN 61
#define WPAD 64
#define W0 195
#define PP (BB*NN)

// ---------------- scratch (device globals; no cudaMalloc allowed) -------------
__device__ float g_h  [PP*WPAD*CC];   // GAT-projected features, window layout
__device__ float g_es [PP*WPAD*HH];
__device__ float g_ed [PP*WPAD*HH];
__device__ float g_cur[PP*WPAD*CC];   // TCN "cur" buffer (channels-last (p,t,c))
__device__ float g_tmp[PP*WPAD*CC];   // TCN intermediate "o"
__device__ float g_ab [8*2*CC];       // fused BN alpha/beta per conv
__device__ float g_wt [8*3*CC*CC];    // weights transposed to [conv][k][ci][co]

__device__ __forceinline__ float gelu_exact(float v){
    return 0.5f*v*(1.0f + erff(v*0.70710678118654752440f));
}

// ---------------- prep: fused BN params ---------------------------------------
__global__ void prep_ab_kernel(const float* c1b, const float* c2b,
    const float* bn1s, const float* bn1b, const float* bn1m, const float* bn1v,
    const float* bn2s, const float* bn2b, const float* bn2m, const float* bn2v){
    int i = blockIdx.x*blockDim.x + threadIdx.x;
    if (i >= 8*CC) return;
    int c = i >> 7, co = i & 127;
    int l = c >> 1;
    const float *s, *bb, *m, *v, *bias;
    if (c & 1){ s=bn2s; bb=bn2b; m=bn2m; v=bn2v; bias=c2b; }
    else      { s=bn1s; bb=bn1b; m=bn1m; v=bn1v; bias=c1b; }
    int gi = l*CC + co;
    float alpha = s[gi]*rsqrtf(v[gi] + 1e-5f);
    float beta  = (bias[gi] - m[gi])*alpha + bb[gi];
    g_ab[c*2*CC + co]      = alpha;
    g_ab[c*2*CC + CC + co] = beta;
}

// ---------------- prep: transpose conv weights to [conv][k][ci][co] -----------
__global__ void prep_wt_kernel(const float* c1w, const float* c2w){
    int i = blockIdx.x*blockDim.x + threadIdx.x;
    if (i >= 8*3*CC*CC) return;
    int co = i & 127;
    int ci = (i >> 7) & 127;
    int kc = i >> 14;            // = c*3 + k
    int k  = kc % 3, c = kc / 3;
    int l  = c >> 1;
    const float* w = (c & 1) ? c2w : c1w;          // (L, CO, CI, K)
    g_wt[i] = w[((l*CC + co)*CC + ci)*3 + k];
}

// ---------------- GAT projection + e_src/e_dst (window only) ------------------
__global__ void proj_kernel(const float* __restrict__ x, const float* __restrict__ gat_w,
                            const float* __restrict__ a_src, const float* __restrict__ a_dst){
    __shared__ float wsT[FIN*CC];   // gat_w transposed [f][c] (conflict-free)
    __shared__ float asr[CC], ads[CC];
    __shared__ float xs[FIN];
    int tid = threadIdx.x;
    int p = blockIdx.x;
    for (int i = tid; i < FIN*CC; i += 128){
        int f = i >> 7, c = i & 127;
        wsT[i] = gat_w[c*FIN + f];
    }
    asr[tid] = a_src[tid];
    ads[tid] = a_dst[tid];
    __syncthreads();
    for (int wi = 0; wi < 16; wi++){
        int wk = blockIdx.y*16 + wi;
        if (wk >= WKN) break;
        if (tid < FIN) xs[tid] = x[((size_t)p*WW + (W0 + wk))*FIN + tid];
        __syncthreads();
        float acc = 0.f;
        #pragma unroll
        for (int f = 0; f < FIN; f++) acc = fmaf(xs[f], wsT[f*CC + tid], acc);
        int base = p*WPAD + wk;
        g_h[base*CC + tid] = acc;
        float es = acc*asr[tid], ed = acc*ads[tid];
        #pragma unroll
        for (int o = 16; o; o >>= 1){
            es += __shfl_xor_sync(0xffffffffu, es, o);
            ed += __shfl_xor_sync(0xffffffffu, ed, o);
        }
        if ((tid & 31) == 0){
            g_es[base*HH + (tid >> 5)] = es;
            g_ed[base*HH + (tid >> 5)] = ed;
        }
        __syncthreads();
    }
}

// ---------------- attention + aggregate + LayerNorm ---------------------------
#define ATTN_SMEM_BYTES (12112*4 + 1600)
__global__ void attn_kernel(const float* __restrict__ adj,
                            const float* __restrict__ ln_g, const float* __restrict__ ln_b){
    extern __shared__ float sm[];
    float* sh_h    = sm;            // 40*128 = 5120
    float* sh_attn = sm + 5120;     // 160*40 = 6400
    float* sh_es   = sm + 11520;    // 160
    float* sh_ed   = sm + 11680;    // 160
    float* sh_red  = sm + 11840;    // 16
    float* sh_ln   = sm + 11856;    // 256
    unsigned char* sh_adj = (unsigned char*)(sm + 12112); // 1600 bytes
    int tid = threadIdx.x;
    int wk = blockIdx.x, b = blockIdx.y;

    for (int i = tid; i < NN*CC; i += 256){
        int j = i >> 7, c = i & 127;
        sh_h[i] = g_h[((b*NN + j)*WPAD + wk)*CC + c];
    }
    for (int i = tid; i < NN*HH; i += 256){
        int j = i >> 2, h = i & 3;
        int gi = ((b*NN + j)*WPAD + wk)*HH + h;
        sh_es[i] = g_es[gi];
        sh_ed[i] = g_ed[gi];
    }
    for (int i = tid; i < NN*NN; i += 256) sh_adj[i] = (adj[i] != 0.f);
    for (int i = tid; i < CC; i += 256){ sh_ln[i] = ln_g[i]; sh_ln[CC + i] = ln_b[i]; }
    __syncthreads();

    if (tid < NN*HH){
        int n = tid >> 2, h = tid & 3;
        float esrc = sh_es[tid];
        float mx = -1e30f;
        #pragma unroll
        for (int j = 0; j < NN; j++){
            float s = esrc + sh_ed[j*HH + h];
            s = s > 0.f ? s : 0.2f*s;
            if (!sh_adj[n*NN + j]) s = -1e9f;
            mx = fmaxf(mx, s);
        }
        float sum = 0.f;
        #pragma unroll
        for (int j = 0; j < NN; j++){
            float s = esrc + sh_ed[j*HH + h];
            s = s > 0.f ? s : 0.2f*s;
            if (!sh_adj[n*NN + j]) s = -1e9f;
            float e = expf(s - mx);
            sum += e;
            sh_attn[tid*NN + j] = e;
        }
        float inv = 1.f/sum;
        for (int j = 0; j < NN; j++) sh_attn[tid*NN + j] *= inv;
    }
    __syncthreads();

    int half = tid >> 7, c = tid & 127, wr = (tid >> 5) & 3;
    int h = c >> 5;
    for (int q = 0; q < 20; q++){
        int n = q*2 + half;
        const float* arow = &sh_attn[(n*HH + h)*NN];
        float acc = 0.f;
        #pragma unroll
        for (int j = 0; j < NN; j++) acc = fmaf(arow[j], sh_h[j*CC + c], acc);
        float v = acc, v2 = acc*acc;
        #pragma unroll
        for (int o = 16; o; o >>= 1){
            v  += __shfl_xor_sync(0xffffffffu, v,  o);
            v2 += __shfl_xor_sync(0xffffffffu, v2, o);
        }
        if ((tid & 31) == 0){ sh_red[half*8 + wr*2] = v; sh_red[half*8 + wr*2 + 1] = v2; }
        __syncthreads();
        float s1 = sh_red[half*8+0] + sh_red[half*8+2] + sh_red[half*8+4] + sh_red[half*8+6];
        float s2 = sh_red[half*8+1] + sh_red[half*8+3] + sh_red[half*8+5] + sh_red[half*8+7];
        float mu  = s1*(1.f/CC);
        float var = s2*(1.f/CC) - mu*mu;
        float g = (acc - mu)*rsqrtf(var + 1e-5f)*sh_ln[c] + sh_ln[CC + c];
        g_cur[((b*NN + n)*WPAD + wk)*CC + c] = g;
        __syncthreads();
    }
}

// ---------------- dilated causal conv + BN + GELU (+ residual GELU) -----------
// dir==0: in=g_cur -> out=g_tmp (no residual)
// dir==1: in=g_tmp -> out=g_cur, residual=g_cur (in-place per-element, safe)
template<int DIL>
__global__ void __launch_bounds__(256,2) conv_kernel(int cidx, int t_lo, int dir){
    constexpr int TP   = 64 + 2*DIL + 1;  // odd pitch -> conflict-free
    constexpr int NROW = 64 + 2*DIL;
    extern __shared__ float sm[];
    float* s_in = sm;            // CC * TP, layout [ci][s]
    float* s_w  = sm + CC*TP;    // CC * CC, layout [ci][co]
    const float* in  = dir ? g_tmp : g_cur;
    float*       out = dir ? g_cur : g_tmp;
    const float* res = dir ? g_cur : nullptr;
    int p = blockIdx.x, tid = threadIdx.x;

    for (int i = tid; i < CC*NROW; i += 256){
        int ci = i & 127, s = i >> 7;
        int t_in = s - 2*DIL;
        float v = (t_in >= 0) ? in[(p*WPAD + t_in)*CC + ci] : 0.f;
        s_in[ci*TP + s] = v;
    }

    int tx = tid & 15, ty = tid >> 4;
    int co0 = tx*8, t0 = ty*4;
    float acc[4][8];
    #pragma unroll
    for (int a = 0; a < 4; a++)
        #pragma unroll
        for (int q = 0; q < 8; q++) acc[a][q] = 0.f;
    bool active = (t0 + 3 >= t_lo);

    #pragma unroll
    for (int k = 0; k < 3; k++){
        __syncthreads();
        const float* wsrc = &g_wt[(cidx*3 + k)*CC*CC];
        for (int i = tid; i < CC*CC; i += 256) s_w[i] = wsrc[i];
        __syncthreads();
        if (active){
            int sb = t0 + k*DIL;
            #pragma unroll 4
            for (int ci = 0; ci < CC; ci++){
                float av[4];
                av[0] = s_in[ci*TP + sb + 0];
                av[1] = s_in[ci*TP + sb + 1];
                av[2] = s_in[ci*TP + sb + 2];
                av[3] = s_in[ci*TP + sb + 3];
                float4 w0 = *(const float4*)&s_w[ci*CC + co0];
                float4 w1 = *(const float4*)&s_w[ci*CC + co0 + 4];
                float wv[8] = {w0.x,w0.y,w0.z,w0.w,w1.x,w1.y,w1.z,w1.w};
                #pragma unroll
                for (int tt = 0; tt < 4; tt++)
                    #pragma unroll
                    for (int q = 0; q < 8; q++)
                        acc[tt][q] = fmaf(av[tt], wv[q], acc[tt][q]);
            }
        }
    }

    const float* al = &g_ab[cidx*2*CC];
    const float* be = al + CC;
    float a8[8], b8[8];
    #pragma unroll
    for (int q = 0; q < 8; q++){ a8[q] = al[co0+q]; b8[q] = be[co0+q]; }
    #pragma unroll
    for (int tt = 0; tt < 4; tt++){
        int t = t0 + tt;
        float* op = &out[(p*WPAD + t)*CC + co0];
        float yv[8];
        #pragma unroll
        for (int q = 0; q < 8; q++)
            yv[q] = gelu_exact(fmaf(acc[tt][q], a8[q], b8[q]));
        if (res){
            float4 r0 = *(const float4*)&res[(p*WPAD + t)*CC + co0];
            float4 r1 = *(const float4*)&res[(p*WPAD + t)*CC + co0 + 4];
            float rv[8] = {r0.x,r0.y,r0.z,r0.w,r1.x,r1.y,r1.z,r1.w};
            #pragma unroll
            for (int q = 0; q < 8; q++) yv[q] = gelu_exact(yv[q] + rv[q]);
        }
        *(float4*)op       = make_float4(yv[0],yv[1],yv[2],yv[3]);
        *(float4*)(op + 4) = make_float4(yv[4],yv[5],yv[6],yv[7]);
    }
}

// ---------------- head: FC(128->128)+GELU, FC(128->1) -------------------------
__global__ void head_kernel(const float* __restrict__ f1w, const float* __restrict__ f1b,
                            const float* __restrict__ f2w, const float* __restrict__ f2b,
                            float* __restrict__ out){
    __shared__ float tv[CC];
    __shared__ float red[4];
    int tid = threadIdx.x;
    int b = blockIdx.x / 7, n = blockIdx.x % 7;
    tv[tid] = g_cur[((b*NN + n)*WPAD + (WKN-1))*CC + tid];
    __syncthreads();
    float z = f1b[tid];
    #pragma unroll 4
    for (int c = 0; c < CC; c++) z = fmaf(f1w[tid*CC + c], tv[c], z);
    z = gelu_exact(z);
    float r = z*f2w[tid];
    #pragma unroll
    for (int o = 16; o; o >>= 1) r += __shfl_xor_sync(0xffffffffu, r, o);
    if ((tid & 31) == 0) red[tid >> 5] = r;
    __syncthreads();
    if (tid == 0) out[blockIdx.x] = red[0] + red[1] + red[2] + red[3] + f2b[0];
}

// -------------------------------------------------------------------------------
static inline int conv_smem(int dil){ return (CC*(64 + 2*dil + 1) + CC*CC)*4; }

extern "C" void kernel_launch(void* const* d_in, const int* in_sizes, int n_in,
                              void* d_out, int out_size){
    const float* x     = (const float*)d_in[0];
    const float* adj   = (const float*)d_in[1];
    const float* gat_w = (const float*)d_in[2];
    const float* a_src = (const float*)d_in[3];
    const float* a_dst = (const float*)d_in[4];
    const float* ln_g  = (const float*)d_in[5];
    const float* ln_b  = (const float*)d_in[6];
    const float* c1w   = (const float*)d_in[7];
    const float* c1b   = (const float*)d_in[8];
    const float* c2w   = (const float*)d_in[9];
    const float* c2b   = (const float*)d_in[10];
    const float* bn1s  = (const float*)d_in[11];
    const float* bn1b  = (const float*)d_in[12];
    const float* bn1m  = (const float*)d_in[13];
    const float* bn1v  = (const float*)d_in[14];
    const float* bn2s  = (const float*)d_in[15];
    const float* bn2b  = (const float*)d_in[16];
    const float* bn2m  = (const float*)d_in[17];
    const float* bn2v  = (const float*)d_in[18];
    const float* f1w   = (const float*)d_in[19];
    const float* f1b   = (const float*)d_in[20];
    const float* f2w   = (const float*)d_in[21];
    const float* f2b   = (const float*)d_in[22];
    float* out = (float*)d_out;

    cudaFuncSetAttribute(attn_kernel,    cudaFuncAttributeMaxDynamicSharedMemorySize, ATTN_SMEM_BYTES);
    cudaFuncSetAttribute(conv_kernel<1>, cudaFuncAttributeMaxDynamicSharedMemorySize, conv_smem(1));
    cudaFuncSetAttribute(conv_kernel<2>, cudaFuncAttributeMaxDynamicSharedMemorySize, conv_smem(2));
    cudaFuncSetAttribute(conv_kernel<4>, cudaFuncAttributeMaxDynamicSharedMemorySize, conv_smem(4));
    cudaFuncSetAttribute(conv_kernel<8>, cudaFuncAttributeMaxDynamicSharedMemorySize, conv_smem(8));

    prep_ab_kernel<<<4, 256>>>(c1b, c2b, bn1s, bn1b, bn1m, bn1v, bn2s, bn2b, bn2m, bn2v);
    prep_wt_kernel<<<(8*3*CC*CC)/256, 256>>>(c1w, c2w);
    proj_kernel<<<dim3(PP, 4), 128>>>(x, gat_w, a_src, a_dst);
    attn_kernel<<<dim3(WKN, BB), 256, ATTN_SMEM_BYTES>>>(adj, ln_g, ln_b);

    // TCN blocks: window receptive-field pruning (t_lo per conv)
    conv_kernel<1><<<PP, 256, conv_smem(1)>>>(0,  2, 0);
    conv_kernel<1><<<PP, 256, conv_smem(1)>>>(1,  4, 1);
    conv_kernel<2><<<PP, 256, conv_smem(2)>>>(2,  8, 0);
    conv_kernel<2><<<PP, 256, conv_smem(2)>>>(3, 12, 1);
    conv_kernel<4><<<PP, 256, conv_smem(4)>>>(4, 20, 0);
    conv_kernel<4><<<PP, 256, conv_smem(4)>>>(5, 28, 1);
    conv_kernel<8><<<PP, 256, conv_smem(8)>>>(6, 44, 0);
    conv_kernel<8><<<PP, 256, conv_smem(8)>>>(7, 60, 1);

    head_kernel<<<BB*7, 128>>>(f1w, f1b, f2w, f2b, out);
}

// round 2
// speedup vs baseline: 1.1186x; 1.1186x over previous
#include <cuda_runtime.h>
#include <math.h>

#define BB 64
#define NN 40
#define WW 256
#define FIN 64
#define HH 4
#define CC 128
#define WKN 61
#define WPAD 64
#define W0 195
#define PP (BB*NN)

// ---------------- scratch (device globals; no cudaMalloc allowed) -------------
__device__ float g_h  [PP*WPAD*CC];   // GAT-projected features, window layout
__device__ float g_es [PP*WPAD*HH];
__device__ float g_ed [PP*WPAD*HH];
__device__ float g_cur[PP*WPAD*CC];   // TCN "cur" buffer (channels-last (p,t,c))
__device__ float g_tmp[PP*WPAD*CC];   // TCN intermediate "o"
__device__ float g_ab [8*2*CC];       // fused BN alpha/beta per conv
__device__ float g_wt [8*3*CC*CC];    // weights transposed to [conv][k][ci][co]

__device__ __forceinline__ float gelu_exact(float v){
    return 0.5f*v*(1.0f + erff(v*0.70710678118654752440f));
}

// packed dual-fp32 FMA (sm_100+; bit-exact IEEE fp32 x2, same pipe, 2 FLOP/lane/inst)
#define FMA_F32X2(d, a, b, c) \
    asm("fma.rn.f32x2 %0, %1, %2, %3;" : "=l"(d) : "l"(a), "l"(b), "l"(c))
#define DUP_F32X2(d, s) \
    asm("mov.b64 %0, {%1, %1};" : "=l"(d) : "r"(__float_as_uint(s)))

// ---------------- prep: fused BN params ---------------------------------------
__global__ void prep_ab_kernel(const float* c1b, const float* c2b,
    const float* bn1s, const float* bn1b, const float* bn1m, const float* bn1v,
    const float* bn2s, const float* bn2b, const float* bn2m, const float* bn2v){
    int i = blockIdx.x*blockDim.x + threadIdx.x;
    if (i >= 8*CC) return;
    int c = i >> 7, co = i & 127;
    int l = c >> 1;
    const float *s, *bb, *m, *v, *bias;
    if (c & 1){ s=bn2s; bb=bn2b; m=bn2m; v=bn2v; bias=c2b; }
    else      { s=bn1s; bb=bn1b; m=bn1m; v=bn1v; bias=c1b; }
    int gi = l*CC + co;
    float alpha = s[gi]*rsqrtf(v[gi] + 1e-5f);
    float beta  = (bias[gi] - m[gi])*alpha + bb[gi];
    g_ab[c*2*CC + co]      = alpha;
    g_ab[c*2*CC + CC + co] = beta;
}

// ---------------- prep: transpose conv weights to [conv][k][ci][co] -----------
__global__ void prep_wt_kernel(const float* c1w, const float* c2w){
    int i = blockIdx.x*blockDim.x + threadIdx.x;
    if (i >= 8*3*CC*CC) return;
    int co = i & 127;
    int ci = (i >> 7) & 127;
    int kc = i >> 14;            // = c*3 + k
    int k  = kc % 3, c = kc / 3;
    int l  = c >> 1;
    const float* w = (c & 1) ? c2w : c1w;          // (L, CO, CI, K)
    g_wt[i] = w[((l*CC + co)*CC + ci)*3 + k];
}

// ---------------- GAT projection + e_src/e_dst (window only) ------------------
__global__ void proj_kernel(const float* __restrict__ x, const float* __restrict__ gat_w,
                            const float* __restrict__ a_src, const float* __restrict__ a_dst){
    __shared__ float wsT[FIN*CC];   // gat_w transposed [f][c] (conflict-free)
    __shared__ float asr[CC], ads[CC];
    __shared__ float xs[FIN];
    int tid = threadIdx.x;
    int p = blockIdx.x;
    for (int i = tid; i < FIN*CC; i += 128){
        int f = i >> 7, c = i & 127;
        wsT[i] = gat_w[c*FIN + f];
    }
    asr[tid] = a_src[tid];
    ads[tid] = a_dst[tid];
    __syncthreads();
    for (int wi = 0; wi < 16; wi++){
        int wk = blockIdx.y*16 + wi;
        if (wk >= WKN) break;
        if (tid < FIN) xs[tid] = x[((size_t)p*WW + (W0 + wk))*FIN + tid];
        __syncthreads();
        float acc = 0.f;
        #pragma unroll
        for (int f = 0; f < FIN; f++) acc = fmaf(xs[f], wsT[f*CC + tid], acc);
        int base = p*WPAD + wk;
        g_h[base*CC + tid] = acc;
        float es = acc*asr[tid], ed = acc*ads[tid];
        #pragma unroll
        for (int o = 16; o; o >>= 1){
            es += __shfl_xor_sync(0xffffffffu, es, o);
            ed += __shfl_xor_sync(0xffffffffu, ed, o);
        }
        if ((tid & 31) == 0){
            g_es[base*HH + (tid >> 5)] = es;
            g_ed[base*HH + (tid >> 5)] = ed;
        }
        __syncthreads();
    }
}

// ---------------- attention + aggregate + LayerNorm ---------------------------
#define ATTN_SMEM_BYTES (12144*4 + 1600)
__global__ void attn_kernel(const float* __restrict__ adj,
                            const float* __restrict__ ln_g, const float* __restrict__ ln_b){
    extern __shared__ float sm[];
    float* sh_h    = sm;            // 40*128 = 5120
    float* sh_attn = sm + 5120;     // 160*40 = 6400
    float* sh_es   = sm + 11520;    // 160
    float* sh_ed   = sm + 11680;    // 160
    float* sh_red  = sm + 11840;    // 32 (two parity banks of 16)
    float* sh_ln   = sm + 11872;    // 256
    unsigned char* sh_adj = (unsigned char*)(sm + 12144); // 1600 bytes
    int tid = threadIdx.x;
    int wk = blockIdx.x, b = blockIdx.y;

    for (int i = tid; i < NN*CC; i += 256){
        int j = i >> 7, c = i & 127;
        sh_h[i] = g_h[((b*NN + j)*WPAD + wk)*CC + c];
    }
    for (int i = tid; i < NN*HH; i += 256){
        int j = i >> 2, h = i & 3;
        int gi = ((b*NN + j)*WPAD + wk)*HH + h;
        sh_es[i] = g_es[gi];
        sh_ed[i] = g_ed[gi];
    }
    for (int i = tid; i < NN*NN; i += 256) sh_adj[i] = (adj[i] != 0.f);
    for (int i = tid; i < CC; i += 256){ sh_ln[i] = ln_g[i]; sh_ln[CC + i] = ln_b[i]; }
    __syncthreads();

    if (tid < NN*HH){
        int n = tid >> 2, h = tid & 3;
        float esrc = sh_es[tid];
        float mx = -1e30f;
        #pragma unroll
        for (int j = 0; j < NN; j++){
            float s = esrc + sh_ed[j*HH + h];
            s = s > 0.f ? s : 0.2f*s;
            if (!sh_adj[n*NN + j]) s = -1e9f;
            mx = fmaxf(mx, s);
        }
        float sum = 0.f;
        #pragma unroll
        for (int j = 0; j < NN; j++){
            float s = esrc + sh_ed[j*HH + h];
            s = s > 0.f ? s : 0.2f*s;
            if (!sh_adj[n*NN + j]) s = -1e9f;
            float e = expf(s - mx);
            sum += e;
            sh_attn[tid*NN + j] = e;
        }
        float inv = 1.f/sum;
        for (int j = 0; j < NN; j++) sh_attn[tid*NN + j] *= inv;
    }
    __syncthreads();

    int half = tid >> 7, c = tid & 127, wr = (tid >> 5) & 3;
    int h = c >> 5;
    for (int q = 0; q < 20; q++){
        int n = q*2 + half;
        float* red = &sh_red[(q & 1)*16];   // parity-indexed -> single sync per iter
        const float* arow = &sh_attn[(n*HH + h)*NN];
        float acc = 0.f;
        #pragma unroll
        for (int j = 0; j < NN; j++) acc = fmaf(arow[j], sh_h[j*CC + c], acc);
        float v = acc, v2 = acc*acc;
        #pragma unroll
        for (int o = 16; o; o >>= 1){
            v  += __shfl_xor_sync(0xffffffffu, v,  o);
            v2 += __shfl_xor_sync(0xffffffffu, v2, o);
        }
        if ((tid & 31) == 0){ red[half*8 + wr*2] = v; red[half*8 + wr*2 + 1] = v2; }
        __syncthreads();
        float s1 = red[half*8+0] + red[half*8+2] + red[half*8+4] + red[half*8+6];
        float s2 = red[half*8+1] + red[half*8+3] + red[half*8+5] + red[half*8+7];
        float mu  = s1*(1.f/CC);
        float var = s2*(1.f/CC) - mu*mu;
        float g = (acc - mu)*rsqrtf(var + 1e-5f)*sh_ln[c] + sh_ln[CC + c];
        g_cur[((b*NN + n)*WPAD + wk)*CC + c] = g;
    }
}

// ---------------- dilated causal conv + BN + GELU (+ residual GELU) -----------
// dir==0: in=g_cur -> out=g_tmp (no residual)
// dir==1: in=g_tmp -> out=g_cur, residual=g_cur (in-place per-element, safe)
template<int DIL>
__global__ void __launch_bounds__(256,2) conv_kernel(int cidx, int t_lo, int dir){
    constexpr int TP   = 64 + 2*DIL + 1;  // odd pitch -> conflict-free
    constexpr int NROW = 64 + 2*DIL;
    extern __shared__ float sm[];
    float* s_in = sm;            // CC * TP, layout [ci][s]
    float* s_w  = sm + CC*TP;    // CC * CC, layout [ci][co]
    const float* in  = dir ? g_tmp : g_cur;
    float*       out = dir ? g_cur : g_tmp;
    const float* res = dir ? g_cur : nullptr;
    int p = blockIdx.x, tid = threadIdx.x;

    for (int i = tid; i < CC*NROW; i += 256){
        int ci = i & 127, s = i >> 7;
        int t_in = s - 2*DIL;
        float v = (t_in >= 0) ? in[(p*WPAD + t_in)*CC + ci] : 0.f;
        s_in[ci*TP + s] = v;
    }

    int tx = tid & 15, ty = tid >> 4;
    int co0 = tx*8, t0 = ty*4;
    // packed-f32x2 accumulators: [t][co-pair], pair = (co0+2q, co0+2q+1)
    unsigned long long acc2[4][4];
    #pragma unroll
    for (int a = 0; a < 4; a++)
        #pragma unroll
        for (int q = 0; q < 4; q++) acc2[a][q] = 0ull;
    bool active = (t0 + 3 >= t_lo);

    #pragma unroll
    for (int k = 0; k < 3; k++){
        __syncthreads();
        const float4* wsrc = (const float4*)&g_wt[(cidx*3 + k)*CC*CC];
        float4* wdst = (float4*)s_w;
        #pragma unroll 4
        for (int i = tid; i < CC*CC/4; i += 256) wdst[i] = wsrc[i];
        __syncthreads();
        if (active){
            int sb = t0 + k*DIL;
            #pragma unroll 2
            for (int ci = 0; ci < CC; ci++){
                const float* ip = &s_in[ci*TP + sb];
                unsigned long long av2[4];
                #pragma unroll
                for (int tt = 0; tt < 4; tt++) DUP_F32X2(av2[tt], ip[tt]);
                ulonglong2 wA = *(const ulonglong2*)&s_w[ci*CC + co0];
                ulonglong2 wB = *(const ulonglong2*)&s_w[ci*CC + co0 + 4];
                unsigned long long wv[4] = {wA.x, wA.y, wB.x, wB.y};
                #pragma unroll
                for (int tt = 0; tt < 4; tt++)
                    #pragma unroll
                    for (int q = 0; q < 4; q++)
                        FMA_F32X2(acc2[tt][q], av2[tt], wv[q], acc2[tt][q]);
            }
        }
    }

    const float* al = &g_ab[cidx*2*CC];
    const float* be = al + CC;
    float a8[8], b8[8];
    #pragma unroll
    for (int q = 0; q < 8; q++){ a8[q] = al[co0+q]; b8[q] = be[co0+q]; }
    #pragma unroll
    for (int tt = 0; tt < 4; tt++){
        int t = t0 + tt;
        float* op = &out[(p*WPAD + t)*CC + co0];
        float accv[8];
        #pragma unroll
        for (int q = 0; q < 4; q++){
            unsigned int lo, hi;
            asm("mov.b64 {%0, %1}, %2;" : "=r"(lo), "=r"(hi) : "l"(acc2[tt][q]));
            accv[2*q]   = __uint_as_float(lo);
            accv[2*q+1] = __uint_as_float(hi);
        }
        float yv[8];
        #pragma unroll
        for (int q = 0; q < 8; q++)
            yv[q] = gelu_exact(fmaf(accv[q], a8[q], b8[q]));
        if (res){
            float4 r0 = *(const float4*)&res[(p*WPAD + t)*CC + co0];
            float4 r1 = *(const float4*)&res[(p*WPAD + t)*CC + co0 + 4];
            float rv[8] = {r0.x,r0.y,r0.z,r0.w,r1.x,r1.y,r1.z,r1.w};
            #pragma unroll
            for (int q = 0; q < 8; q++) yv[q] = gelu_exact(yv[q] + rv[q]);
        }
        *(float4*)op       = make_float4(yv[0],yv[1],yv[2],yv[3]);
        *(float4*)(op + 4) = make_float4(yv[4],yv[5],yv[6],yv[7]);
    }
}

// ---------------- head: FC(128->128)+GELU, FC(128->1) -------------------------
__global__ void head_kernel(const float* __restrict__ f1w, const float* __restrict__ f1b,
                            const float* __restrict__ f2w, const float* __restrict__ f2b,
                            float* __restrict__ out){
    __shared__ float tv[CC];
    __shared__ float red[4];
    int tid = threadIdx.x;
    int b = blockIdx.x / 7, n = blockIdx.x % 7;
    tv[tid] = g_cur[((b*NN + n)*WPAD + (WKN-1))*CC + tid];
    __syncthreads();
    float z = f1b[tid];
    #pragma unroll 4
    for (int c = 0; c < CC; c++) z = fmaf(f1w[tid*CC + c], tv[c], z);
    z = gelu_exact(z);
    float r = z*f2w[tid];
    #pragma unroll
    for (int o = 16; o; o >>= 1) r += __shfl_xor_sync(0xffffffffu, r, o);
    if ((tid & 31) == 0) red[tid >> 5] = r;
    __syncthreads();
    if (tid == 0) out[blockIdx.x] = red[0] + red[1] + red[2] + red[3] + f2b[0];
}

// -------------------------------------------------------------------------------
static inline int conv_smem(int dil){ return (CC*(64 + 2*dil + 1) + CC*CC)*4; }

extern "C" void kernel_launch(void* const* d_in, const int* in_sizes, int n_in,
                              void* d_out, int out_size){
    const float* x     = (const float*)d_in[0];
    const float* adj   = (const float*)d_in[1];
    const float* gat_w = (const float*)d_in[2];
    const float* a_src = (const float*)d_in[3];
    const float* a_dst = (const float*)d_in[4];
    const float* ln_g  = (const float*)d_in[5];
    const float* ln_b  = (const float*)d_in[6];
    const float* c1w   = (const float*)d_in[7];
    const float* c1b   = (const float*)d_in[8];
    const float* c2w   = (const float*)d_in[9];
    const float* c2b   = (const float*)d_in[10];
    const float* bn1s  = (const float*)d_in[11];
    const float* bn1b  = (const float*)d_in[12];
    const float* bn1m  = (const float*)d_in[13];
    const float* bn1v  = (const float*)d_in[14];
    const float* bn2s  = (const float*)d_in[15];
    const float* bn2b  = (const float*)d_in[16];
    const float* bn2m  = (const float*)d_in[17];
    const float* bn2v  = (const float*)d_in[18];
    const float* f1w   = (const float*)d_in[19];
    const float* f1b   = (const float*)d_in[20];
    const float* f2w   = (const float*)d_in[21];
    const float* f2b   = (const float*)d_in[22];
    float* out = (float*)d_out;

    cudaFuncSetAttribute(attn_kernel,    cudaFuncAttributeMaxDynamicSharedMemorySize, ATTN_SMEM_BYTES);
    cudaFuncSetAttribute(conv_kernel<1>, cudaFuncAttributeMaxDynamicSharedMemorySize, conv_smem(1));
    cudaFuncSetAttribute(conv_kernel<2>, cudaFuncAttributeMaxDynamicSharedMemorySize, conv_smem(2));
    cudaFuncSetAttribute(conv_kernel<4>, cudaFuncAttributeMaxDynamicSharedMemorySize, conv_smem(4));
    cudaFuncSetAttribute(conv_kernel<8>, cudaFuncAttributeMaxDynamicSharedMemorySize, conv_smem(8));

    prep_ab_kernel<<<4, 256>>>(c1b, c2b, bn1s, bn1b, bn1m, bn1v, bn2s, bn2b, bn2m, bn2v);
    prep_wt_kernel<<<(8*3*CC*CC)/256, 256>>>(c1w, c2w);
    proj_kernel<<<dim3(PP, 4), 128>>>(x, gat_w, a_src, a_dst);
    attn_kernel<<<dim3(WKN, BB), 256, ATTN_SMEM_BYTES>>>(adj, ln_g, ln_b);

    // TCN blocks: window receptive-field pruning (t_lo per conv)
    conv_kernel<1><<<PP, 256, conv_smem(1)>>>(0,  2, 0);
    conv_kernel<1><<<PP, 256, conv_smem(1)>>>(1,  4, 1);
    conv_kernel<2><<<PP, 256, conv_smem(2)>>>(2,  8, 0);
    conv_kernel<2><<<PP, 256, conv_smem(2)>>>(3, 12, 1);
    conv_kernel<4><<<PP, 256, conv_smem(4)>>>(4, 20, 0);
    conv_kernel<4><<<PP, 256, conv_smem(4)>>>(5, 28, 1);
    conv_kernel<8><<<PP, 256, conv_smem(8)>>>(6, 44, 0);
    conv_kernel<8><<<PP, 256, conv_smem(8)>>>(7, 60, 1);

    head_kernel<<<BB*7, 128>>>(f1w, f1b, f2w, f2b, out);
}

// round 4
// speedup vs baseline: 1.8883x; 1.6881x over previous
#include <cuda_runtime.h>
#include <cuda_bf16.h>
#include <math.h>
#include <stdint.h>

#define BB 64
#define NN 40
#define WW 256
#define FIN 64
#define HH 4
#define CC 128
#define WKN 61
#define WPAD 64
#define W0 195
#define PP (BB*NN)

// ---------------- scratch (device globals; no cudaMalloc allowed) -------------
__device__ __align__(128) float g_h  [PP*WPAD*CC];
__device__ __align__(128) float g_es [PP*WPAD*HH];
__device__ __align__(128) float g_ed [PP*WPAD*HH];
__device__ __align__(128) float g_cur[PP*WPAD*CC];
__device__ __align__(128) float g_tmp[PP*WPAD*CC];
__device__ __align__(128) float g_ab [8*2*CC];
// bf16 hi/lo weights in mma B-fragment order:
// index = ((((conv*3+tap)*2+part)*8+kt)*16+nt)*32+lane  -> uint2 (2 regs)
__device__ __align__(128) uint2 g_wb[8*3*2*8*16*32];

__device__ __forceinline__ float gelu_exact(float v){
    return 0.5f*v*(1.0f + erff(v*0.70710678118654752440f));
}

// split a float2 into packed bf16x2 hi and lo (residual) parts
__device__ __forceinline__ void split_pair(float x, float y, uint32_t& hi, uint32_t& lo){
    __nv_bfloat162 h = __floats2bfloat162_rn(x, y);
    float hx = __bfloat162float(h.x), hy = __bfloat162float(h.y);
    __nv_bfloat162 l = __floats2bfloat162_rn(x - hx, y - hy);
    hi = *(uint32_t*)&h;
    lo = *(uint32_t*)&l;
}

#define MMA_BF16(c, a, b) \
    asm volatile("mma.sync.aligned.m16n8k16.row.col.f32.bf16.bf16.f32 " \
        "{%0,%1,%2,%3}, {%4,%5,%6,%7}, {%8,%9}, {%0,%1,%2,%3};" \
        : "+f"((c)[0]), "+f"((c)[1]), "+f"((c)[2]), "+f"((c)[3]) \
        : "r"((a)[0]), "r"((a)[1]), "r"((a)[2]), "r"((a)[3]), \
          "r"((b).x), "r"((b).y))

// ---------------- prep: fused BN params ---------------------------------------
__global__ void prep_ab_kernel(const float* c1b, const float* c2b,
    const float* bn1s, const float* bn1b, const float* bn1m, const float* bn1v,
    const float* bn2s, const float* bn2b, const float* bn2m, const float* bn2v){
    int i = blockIdx.x*blockDim.x + threadIdx.x;
    if (i >= 8*CC) return;
    int c = i >> 7, co = i & 127;
    int l = c >> 1;
    const float *s, *bb, *m, *v, *bias;
    if (c & 1){ s=bn2s; bb=bn2b; m=bn2m; v=bn2v; bias=c2b; }
    else      { s=bn1s; bb=bn1b; m=bn1m; v=bn1v; bias=c1b; }
    int gi = l*CC + co;
    float alpha = s[gi]*rsqrtf(v[gi] + 1e-5f);
    float beta  = (bias[gi] - m[gi])*alpha + bb[gi];
    g_ab[c*2*CC + co]      = alpha;
    g_ab[c*2*CC + CC + co] = beta;
}

// ------- prep: bf16 hi/lo weights in mma B-fragment order ---------------------
__global__ void prep_wb_kernel(const float* c1w, const float* c2w){
    int i = blockIdx.x*blockDim.x + threadIdx.x;
    if (i >= 8*3*2*8*16*32) return;
    int lane = i & 31;
    int nt   = (i >> 5) & 15;
    int kt   = (i >> 9) & 7;
    int part = (i >> 12) & 1;
    int tc   = i >> 13;
    int tap  = tc % 3;
    int c    = tc / 3;
    int l = c >> 1;
    const float* src = (c & 1) ? c2w : c1w;          // (L, CO, CI, K)
    int co  = nt*8 + (lane >> 2);
    int ci0 = kt*16 + (lane & 3)*2;
    float w00 = src[((l*CC+co)*CC + ci0    )*3 + tap];
    float w01 = src[((l*CC+co)*CC + ci0 + 1)*3 + tap];
    float w10 = src[((l*CC+co)*CC + ci0 + 8)*3 + tap];
    float w11 = src[((l*CC+co)*CC + ci0 + 9)*3 + tap];
    uint32_t h0, l0, h1, l1;
    split_pair(w00, w01, h0, l0);
    split_pair(w10, w11, h1, l1);
    g_wb[i] = part ? make_uint2(l0, l1) : make_uint2(h0, h1);
}

// ---------------- GAT projection + e_src/e_dst (window only) ------------------
__global__ void proj_kernel(const float* __restrict__ x, const float* __restrict__ gat_w,
                            const float* __restrict__ a_src, const float* __restrict__ a_dst){
    __shared__ float wsT[FIN*CC];
    __shared__ float asr[CC], ads[CC];
    __shared__ float xs[FIN];
    int tid = threadIdx.x;
    int p = blockIdx.x;
    for (int i = tid; i < FIN*CC; i += 128){
        int f = i >> 7, c = i & 127;
        wsT[i] = gat_w[c*FIN + f];
    }
    asr[tid] = a_src[tid];
    ads[tid] = a_dst[tid];
    __syncthreads();
    for (int wi = 0; wi < 16; wi++){
        int wk = blockIdx.y*16 + wi;
        if (wk >= WKN) break;
        if (tid < FIN) xs[tid] = x[((size_t)p*WW + (W0 + wk))*FIN + tid];
        __syncthreads();
        float acc = 0.f;
        #pragma unroll
        for (int f = 0; f < FIN; f++) acc = fmaf(xs[f], wsT[f*CC + tid], acc);
        int base = p*WPAD + wk;
        g_h[base*CC + tid] = acc;
        float es = acc*asr[tid], ed = acc*ads[tid];
        #pragma unroll
        for (int o = 16; o; o >>= 1){
            es += __shfl_xor_sync(0xffffffffu, es, o);
            ed += __shfl_xor_sync(0xffffffffu, ed, o);
        }
        if ((tid & 31) == 0){
            g_es[base*HH + (tid >> 5)] = es;
            g_ed[base*HH + (tid >> 5)] = ed;
        }
        __syncthreads();
    }
}

// ---------------- attention + aggregate + LayerNorm ---------------------------
#define ATTN_SMEM_BYTES (12144*4 + 1600)
__global__ void attn_kernel(const float* __restrict__ adj,
                            const float* __restrict__ ln_g, const float* __restrict__ ln_b){
    extern __shared__ float sm[];
    float* sh_h    = sm;
    float* sh_attn = sm + 5120;
    float* sh_es   = sm + 11520;
    float* sh_ed   = sm + 11680;
    float* sh_red  = sm + 11840;
    float* sh_ln   = sm + 11872;
    unsigned char* sh_adj = (unsigned char*)(sm + 12144);
    int tid = threadIdx.x;
    int wk = blockIdx.x, b = blockIdx.y;

    for (int i = tid; i < NN*CC; i += 256){
        int j = i >> 7, c = i & 127;
        sh_h[i] = g_h[((b*NN + j)*WPAD + wk)*CC + c];
    }
    for (int i = tid; i < NN*HH; i += 256){
        int j = i >> 2, h = i & 3;
        int gi = ((b*NN + j)*WPAD + wk)*HH + h;
        sh_es[i] = g_es[gi];
        sh_ed[i] = g_ed[gi];
    }
    for (int i = tid; i < NN*NN; i += 256) sh_adj[i] = (adj[i] != 0.f);
    for (int i = tid; i < CC; i += 256){ sh_ln[i] = ln_g[i]; sh_ln[CC + i] = ln_b[i]; }
    __syncthreads();

    if (tid < NN*HH){
        int n = tid >> 2, h = tid & 3;
        float esrc = sh_es[tid];
        float mx = -1e30f;
        #pragma unroll
        for (int j = 0; j < NN; j++){
            float s = esrc + sh_ed[j*HH + h];
            s = s > 0.f ? s : 0.2f*s;
            if (!sh_adj[n*NN + j]) s = -1e9f;
            mx = fmaxf(mx, s);
        }
        float sum = 0.f;
        #pragma unroll
        for (int j = 0; j < NN; j++){
            float s = esrc + sh_ed[j*HH + h];
            s = s > 0.f ? s : 0.2f*s;
            if (!sh_adj[n*NN + j]) s = -1e9f;
            float e = expf(s - mx);
            sum += e;
            sh_attn[tid*NN + j] = e;
        }
        float inv = 1.f/sum;
        for (int j = 0; j < NN; j++) sh_attn[tid*NN + j] *= inv;
    }
    __syncthreads();

    int half = tid >> 7, c = tid & 127, wr = (tid >> 5) & 3;
    int h = c >> 5;
    for (int q = 0; q < 20; q++){
        int n = q*2 + half;
        float* red = &sh_red[(q & 1)*16];
        const float* arow = &sh_attn[(n*HH + h)*NN];
        float acc = 0.f;
        #pragma unroll
        for (int j = 0; j < NN; j++) acc = fmaf(arow[j], sh_h[j*CC + c], acc);
        float v = acc, v2 = acc*acc;
        #pragma unroll
        for (int o = 16; o; o >>= 1){
            v  += __shfl_xor_sync(0xffffffffu, v,  o);
            v2 += __shfl_xor_sync(0xffffffffu, v2, o);
        }
        if ((tid & 31) == 0){ red[half*8 + wr*2] = v; red[half*8 + wr*2 + 1] = v2; }
        __syncthreads();
        float s1 = red[half*8+0] + red[half*8+2] + red[half*8+4] + red[half*8+6];
        float s2 = red[half*8+1] + red[half*8+3] + red[half*8+5] + red[half*8+7];
        float mu  = s1*(1.f/CC);
        float var = s2*(1.f/CC) - mu*mu;
        float g = (acc - mu)*rsqrtf(var + 1e-5f)*sh_ln[c] + sh_ln[CC + c];
        g_cur[((b*NN + n)*WPAD + wk)*CC + c] = g;
    }
}

// ======= conv via mma.sync bf16 (3-term compensated), one window per CTA =======
// D[64 t][128 co] = sum_{tap,ci} in[t + tap*DIL - 2*DIL][ci] * W[co][ci][tap]
template<int DIL>
__global__ void __launch_bounds__(256) conv_mma_kernel(int cidx, int t_lo, int dir){
    constexpr int NROW  = 64 + 2*DIL;
    constexpr int PITCH = 136;
    __shared__ float s_in[NROW*PITCH];
    int tid = threadIdx.x, lane = tid & 31, wid = tid >> 5;
    int p = blockIdx.x;
    const float* in  = dir ? g_tmp : g_cur;
    float*       out = dir ? g_cur : g_tmp;

    // stage input window (with causal left halo, zero-padded)
    for (int i = tid; i < NROW*32; i += 256){
        int s = i >> 5, cg = (i & 31)*4;
        int t_in = s - 2*DIL;
        float4 v = (t_in >= 0) ? *(const float4*)&in[((size_t)p*WPAD + t_in)*CC + cg]
                               : make_float4(0.f, 0.f, 0.f, 0.f);
        *(float4*)&s_in[s*PITCH + cg] = v;
    }
    __syncthreads();

    int wm = wid & 3, wn = wid >> 2;           // m-tile (16 rows), n-half (64 cols)
    float acc[8][4];
    #pragma unroll
    for (int nt = 0; nt < 8; nt++)
        #pragma unroll
        for (int q = 0; q < 4; q++) acc[nt][q] = 0.f;

    bool active = (wm*16 + 15) >= t_lo;
    if (active){
        int r  = lane >> 2;                    // 0..7
        int cp = (lane & 3)*2;                 // 0,2,4,6
        #pragma unroll
        for (int tap = 0; tap < 3; tap++){
            const uint2* wbh = g_wb + ((size_t)((cidx*3 + tap)*2 + 0)*8)*16*32;
            const uint2* wbl = g_wb + ((size_t)((cidx*3 + tap)*2 + 1)*8)*16*32;
            int sbase = (wm*16 + r + tap*DIL)*PITCH;
            #pragma unroll 2
            for (int kt = 0; kt < 8; kt++){
                int c0 = kt*16 + cp;
                float2 v00 = *(const float2*)&s_in[sbase + c0];
                float2 v10 = *(const float2*)&s_in[sbase + 8*PITCH + c0];
                float2 v01 = *(const float2*)&s_in[sbase + c0 + 8];
                float2 v11 = *(const float2*)&s_in[sbase + 8*PITCH + c0 + 8];
                uint32_t ah[4], al[4];
                split_pair(v00.x, v00.y, ah[0], al[0]);
                split_pair(v10.x, v10.y, ah[1], al[1]);
                split_pair(v01.x, v01.y, ah[2], al[2]);
                split_pair(v11.x, v11.y, ah[3], al[3]);
                const uint2* ph = wbh + (kt*16 + wn*8)*32 + lane;
                const uint2* pl = wbl + (kt*16 + wn*8)*32 + lane;
                #pragma unroll
                for (int nt = 0; nt < 8; nt++){
                    uint2 bh = __ldg(ph + nt*32);
                    uint2 bl = __ldg(pl + nt*32);
                    MMA_BF16(acc[nt], ah, bh);
                    MMA_BF16(acc[nt], al, bh);
                    MMA_BF16(acc[nt], ah, bl);
                }
            }
        }
    }

    // epilogue: BN + GELU (+ residual GELU), write fp32
    int r0 = wm*16 + (lane >> 2), r1 = r0 + 8;
    int cbase = wn*64 + (lane & 3)*2;
    const float* ab = &g_ab[cidx*2*CC];
    size_t ob0 = ((size_t)p*WPAD + r0)*CC;
    size_t ob1 = ((size_t)p*WPAD + r1)*CC;
    #pragma unroll
    for (int nt = 0; nt < 8; nt++){
        int c = cbase + nt*8;
        float a0 = ab[c], a1 = ab[c+1], b0 = ab[CC + c], b1 = ab[CC + c + 1];
        float y00 = gelu_exact(fmaf(acc[nt][0], a0, b0));
        float y01 = gelu_exact(fmaf(acc[nt][1], a1, b1));
        float y10 = gelu_exact(fmaf(acc[nt][2], a0, b0));
        float y11 = gelu_exact(fmaf(acc[nt][3], a1, b1));
        if (dir){
            float2 q0 = *(const float2*)&g_cur[ob0 + c];
            float2 q1 = *(const float2*)&g_cur[ob1 + c];
            y00 = gelu_exact(y00 + q0.x);
            y01 = gelu_exact(y01 + q0.y);
            y10 = gelu_exact(y10 + q1.x);
            y11 = gelu_exact(y11 + q1.y);
        }
        *(float2*)&out[ob0 + c] = make_float2(y00, y01);
        *(float2*)&out[ob1 + c] = make_float2(y10, y11);
    }
}

// ---------------- head: FC(128->128)+GELU, FC(128->1) -------------------------
__global__ void head_kernel(const float* __restrict__ f1w, const float* __restrict__ f1b,
                            const float* __restrict__ f2w, const float* __restrict__ f2b,
                            float* __restrict__ out){
    __shared__ float tv[CC];
    __shared__ float red[4];
    int tid = threadIdx.x;
    int b = blockIdx.x / 7, n = blockIdx.x % 7;
    tv[tid] = g_cur[((b*NN + n)*WPAD + (WKN-1))*CC + tid];
    __syncthreads();
    float z = f1b[tid];
    #pragma unroll 4
    for (int c = 0; c < CC; c++) z = fmaf(f1w[tid*CC + c], tv[c], z);
    z = gelu_exact(z);
    float r = z*f2w[tid];
    #pragma unroll
    for (int o = 16; o; o >>= 1) r += __shfl_xor_sync(0xffffffffu, r, o);
    if ((tid & 31) == 0) red[tid >> 5] = r;
    __syncthreads();
    if (tid == 0) out[blockIdx.x] = red[0] + red[1] + red[2] + red[3] + f2b[0];
}

// -------------------------------------------------------------------------------
extern "C" void kernel_launch(void* const* d_in, const int* in_sizes, int n_in,
                              void* d_out, int out_size){
    const float* x     = (const float*)d_in[0];
    const float* adj   = (const float*)d_in[1];
    const float* gat_w = (const float*)d_in[2];
    const float* a_src = (const float*)d_in[3];
    const float* a_dst = (const float*)d_in[4];
    const float* ln_g  = (const float*)d_in[5];
    const float* ln_b  = (const float*)d_in[6];
    const float* c1w   = (const float*)d_in[7];
    const float* c1b   = (const float*)d_in[8];
    const float* c2w   = (const float*)d_in[9];
    const float* c2b   = (const float*)d_in[10];
    const float* bn1s  = (const float*)d_in[11];
    const float* bn1b  = (const float*)d_in[12];
    const float* bn1m  = (const float*)d_in[13];
    const float* bn1v  = (const float*)d_in[14];
    const float* bn2s  = (const float*)d_in[15];
    const float* bn2b  = (const float*)d_in[16];
    const float* bn2m  = (const float*)d_in[17];
    const float* bn2v  = (const float*)d_in[18];
    const float* f1w   = (const float*)d_in[19];
    const float* f1b   = (const float*)d_in[20];
    const float* f2w   = (const float*)d_in[21];
    const float* f2b   = (const float*)d_in[22];
    float* out = (float*)d_out;

    cudaFuncSetAttribute(attn_kernel, cudaFuncAttributeMaxDynamicSharedMemorySize, ATTN_SMEM_BYTES);

    prep_ab_kernel<<<4, 256>>>(c1b, c2b, bn1s, bn1b, bn1m, bn1v, bn2s, bn2b, bn2m, bn2v);
    prep_wb_kernel<<<(8*3*2*8*16*32)/256, 256>>>(c1w, c2w);
    proj_kernel<<<dim3(PP, 4), 128>>>(x, gat_w, a_src, a_dst);
    attn_kernel<<<dim3(WKN, BB), 256, ATTN_SMEM_BYTES>>>(adj, ln_g, ln_b);

    conv_mma_kernel<1><<<PP, 256>>>(0,  2, 0);
    conv_mma_kernel<1><<<PP, 256>>>(1,  4, 1);
    conv_mma_kernel<2><<<PP, 256>>>(2,  8, 0);
    conv_mma_kernel<2><<<PP, 256>>>(3, 12, 1);
    conv_mma_kernel<4><<<PP, 256>>>(4, 20, 0);
    conv_mma_kernel<4><<<PP, 256>>>(5, 28, 1);
    conv_mma_kernel<8><<<PP, 256>>>(6, 44, 0);
    conv_mma_kernel<8><<<PP, 256>>>(7, 60, 1);

    head_kernel<<<BB*7, 128>>>(f1w, f1b, f2w, f2b, out);
}